// round 12
// baseline (speedup 1.0000x reference)
#include <cuda_runtime.h>
#include <cuda_fp16.h>
#include <math.h>
#include <stdint.h>

// ---------------- problem constants ----------------
#define Tn    8192          // B*S tokens
#define Dn    1024          // d_model
#define NCOLSn 32
#define FSn   16
#define NEFn  8
#define En    8
#define DFEn  64
#define DRHn  256
#define DEHn  2048
#define KINn  (Dn + DFEn)   // 1088
#define EPSf  1e-5f

// ---------------- scratch ----------------
__device__ __half g_hln_h [Tn * Dn];
__device__ __half g_hln_l [Tn * Dn];
__device__ __half g_femb_h[Tn * DFEn];
__device__ __half g_femb_l[Tn * DFEn];
__device__ float  g_hr    [Tn * DRHn];
__device__ int    g_cnt   [En];
__device__ int    g_plist [En * Tn];
__device__ int    g_toke  [Tn * 2];
__device__ float  g_tokw  [Tn * 2];
__device__ __half g_eemb_h[Tn * 2 * DFEn];
__device__ __half g_hh_h  [Tn * 2 * DEHn];
__device__ __half g_eo_h  [Tn * 2 * Dn];
__device__ __half g_We1t_h[En * (size_t)KINn * DEHn]; // [e][n][k]
__device__ __half g_We2t_h[En * (size_t)DEHn * Dn];   // [e][n][k]
__device__ __half g_Wr1t_h[(size_t)KINn * DRHn];
__device__ __half g_Wr1t_l[(size_t)KINn * DRHn];

__device__ __forceinline__ float gelu_f(float x) {
    float x3 = x * x * x;
    return 0.5f * x * (1.0f + tanhf(0.7978845608028654f * (x + 0.044715f * x3)));
}

__device__ __forceinline__ void mma_f16(float c[4], const unsigned a[4], const unsigned b[2]) {
    asm volatile(
        "mma.sync.aligned.m16n8k16.row.col.f32.f16.f16.f32 "
        "{%0,%1,%2,%3}, {%4,%5,%6,%7}, {%8,%9}, {%0,%1,%2,%3};"
        : "+f"(c[0]), "+f"(c[1]), "+f"(c[2]), "+f"(c[3])
        : "r"(a[0]), "r"(a[1]), "r"(a[2]), "r"(a[3]), "r"(b[0]), "r"(b[1]));
}

__device__ __forceinline__ uint32_t smem_u32(const void* p) {
    uint32_t a;
    asm("{ .reg .u64 t; cvta.to.shared.u64 t, %1; cvt.u32.u64 %0, t; }" : "=r"(a) : "l"(p));
    return a;
}
__device__ __forceinline__ void cp_async16(uint32_t d, const void* s, int sz) {
    asm volatile("cp.async.cg.shared.global [%0], [%1], 16, %2;"
                 :: "r"(d), "l"(s), "r"(sz) : "memory");
}

// ---------------- K0a: weight transpose+cvt  W[e][K][N] f32 -> Wt[e][N][K] f16 ----------------
__global__ __launch_bounds__(256) void k_transpose_h(
    const float* __restrict__ W, __half* __restrict__ Wt, int K, int N)
{
    __shared__ float tile[32][33];
    const int e = blockIdx.z;
    const float* Wp  = W  + (size_t)e * K * N;
    __half*      Wtp = Wt + (size_t)e * K * N;
    int x = blockIdx.x * 32 + threadIdx.x;   // n
    int y = blockIdx.y * 32 + threadIdx.y;   // k
    #pragma unroll
    for (int i = 0; i < 32; i += 8)
        tile[threadIdx.y + i][threadIdx.x] = Wp[(size_t)(y + i) * N + x];
    __syncthreads();
    x = blockIdx.y * 32 + threadIdx.x;       // k
    y = blockIdx.x * 32 + threadIdx.y;       // n
    #pragma unroll
    for (int i = 0; i < 32; i += 8)
        Wtp[(size_t)(y + i) * K + x] = __float2half(tile[threadIdx.x][threadIdx.y + i]);
}

// ---------------- K0b: transpose with hi/lo split (router W1) ----------------
__global__ __launch_bounds__(256) void k_transpose_hl(
    const float* __restrict__ W, __half* __restrict__ Wth, __half* __restrict__ Wtl,
    int K, int N)
{
    __shared__ float tile[32][33];
    int x = blockIdx.x * 32 + threadIdx.x;   // n
    int y = blockIdx.y * 32 + threadIdx.y;   // k
    #pragma unroll
    for (int i = 0; i < 32; i += 8)
        tile[threadIdx.y + i][threadIdx.x] = W[(size_t)(y + i) * N + x];
    __syncthreads();
    x = blockIdx.y * 32 + threadIdx.x;       // k
    y = blockIdx.x * 32 + threadIdx.y;       // n
    #pragma unroll
    for (int i = 0; i < 32; i += 8) {
        float v = tile[threadIdx.x][threadIdx.y + i];
        __half hi = __float2half(v);
        __half lo = __float2half(v - __half2float(hi));
        Wth[(size_t)(y + i) * K + x] = hi;
        Wtl[(size_t)(y + i) * K + x] = lo;
    }
}

// ---------------- K1: layernorm + stage-feature embedding (+ zero cnt) ----------------
__global__ __launch_bounds__(256) void k_ln(
    const float* __restrict__ h, const float* __restrict__ feat,
    const float* __restrict__ ln_g, const float* __restrict__ ln_b,
    const float* __restrict__ Wsf, const float* __restrict__ bsf,
    const int* __restrict__ stage_idx)
{
    const int t = blockIdx.x;
    const int tid = threadIdx.x;
    if (blockIdx.x == 0 && tid < En) g_cnt[tid] = 0;
    const float4 xv = ((const float4*)(h + (size_t)t * Dn))[tid];

    float s  = xv.x + xv.y + xv.z + xv.w;
    float s2 = xv.x * xv.x + xv.y * xv.y + xv.z * xv.z + xv.w * xv.w;
    #pragma unroll
    for (int o = 16; o > 0; o >>= 1) {
        s  += __shfl_xor_sync(0xffffffffu, s,  o);
        s2 += __shfl_xor_sync(0xffffffffu, s2, o);
    }
    __shared__ float rs[8], rs2[8], stats[2];
    if ((tid & 31) == 0) { rs[tid >> 5] = s; rs2[tid >> 5] = s2; }
    __syncthreads();
    if (tid == 0) {
        float a = 0.f, a2 = 0.f;
        #pragma unroll
        for (int i = 0; i < 8; i++) { a += rs[i]; a2 += rs2[i]; }
        float m = a * (1.0f / Dn);
        stats[0] = m;
        stats[1] = rsqrtf(a2 * (1.0f / Dn) - m * m + EPSf);
    }
    __shared__ float sf[FSn];
    if (tid < FSn) sf[tid] = feat[(size_t)t * NCOLSn + stage_idx[tid]];
    __syncthreads();

    const float m = stats[0], r = stats[1];
    const float4 gv = ((const float4*)ln_g)[tid];
    const float4 bv = ((const float4*)ln_b)[tid];
    float o[4];
    o[0] = (xv.x - m) * r * gv.x + bv.x;
    o[1] = (xv.y - m) * r * gv.y + bv.y;
    o[2] = (xv.z - m) * r * gv.z + bv.z;
    o[3] = (xv.w - m) * r * gv.w + bv.w;
    __half2* dh = (__half2*)(g_hln_h + (size_t)t * Dn);
    __half2* dl = (__half2*)(g_hln_l + (size_t)t * Dn);
    #pragma unroll
    for (int q = 0; q < 2; q++) {
        __half2 hi = __floats2half2_rn(o[2 * q], o[2 * q + 1]);
        float2 hif = __half22float2(hi);
        __half2 lo = __floats2half2_rn(o[2 * q] - hif.x, o[2 * q + 1] - hif.y);
        dh[tid * 2 + q] = hi;
        dl[tid * 2 + q] = lo;
    }

    if (tid < DFEn) {
        float acc = bsf[tid];
        #pragma unroll
        for (int f = 0; f < FSn; f++) acc = fmaf(sf[f], Wsf[f * DFEn + tid], acc);
        __half hi = __float2half(acc);
        g_femb_h[(size_t)t * DFEn + tid] = hi;
        g_femb_l[(size_t)t * DFEn + tid] = __float2half(acc - __half2float(hi));
    }
}

// ================= shared mma fragment macros (R6 layout, conflict-free LDS.32) =================
#define MMA_FRAG_A_S(dst, SM, BUF)                                                \
    _Pragma("unroll")                                                             \
    for (int mi = 0; mi < 4; mi++) {                                              \
        const int r0 = wm + mi * 16 + gid;                                        \
        dst[mi][0] = *(const unsigned*)&SM[BUF][r0][2 * tig];                     \
        dst[mi][1] = *(const unsigned*)&SM[BUF][r0 + 8][2 * tig];                 \
        dst[mi][2] = *(const unsigned*)&SM[BUF][r0][2 * tig + 8];                 \
        dst[mi][3] = *(const unsigned*)&SM[BUF][r0 + 8][2 * tig + 8];             \
    }

#define MMA_FRAG_A_P(dst, AP)                                                     \
    _Pragma("unroll")                                                             \
    for (int mi = 0; mi < 4; mi++) {                                              \
        const int r0 = wm + mi * 16 + gid;                                        \
        dst[mi][0] = *(const unsigned*)&AP[r0][2 * tig];                          \
        dst[mi][1] = *(const unsigned*)&AP[r0 + 8][2 * tig];                      \
        dst[mi][2] = *(const unsigned*)&AP[r0][2 * tig + 8];                      \
        dst[mi][3] = *(const unsigned*)&AP[r0 + 8][2 * tig + 8];                  \
    }
#define MMA_FRAG_B_P(dst, BP)                                                     \
    _Pragma("unroll")                                                             \
    for (int ni = 0; ni < 4; ni++) {                                              \
        const int nr = wn + ni * 8 + gid;                                         \
        dst[ni][0] = *(const unsigned*)&BP[nr][2 * tig];                          \
        dst[ni][1] = *(const unsigned*)&BP[nr][2 * tig + 8];                      \
    }

// ---------------- router GEMM1 (split-fp16, 128M x 64N tiles, 2 CTA/SM) ----------------
__global__ __launch_bounds__(256, 2) void k_router_gemm_split(const float* __restrict__ bias)
{
    __shared__ __half Ah[2][128][24];
    __shared__ __half Al[2][128][24];
    __shared__ __half Bh[2][64][24];
    __shared__ __half Bl[2][64][24];
    const int m0 = blockIdx.y * 128, n0 = blockIdx.x * 64;
    const int tid = threadIdx.x;
    const int warp = tid >> 5, lane = tid & 31;
    const int wm = (warp >> 2) * 64, wn = (warp & 3) * 16;
    const int gid = lane >> 2, tig = lane & 3;
    const int arow = tid >> 1, achk = (tid & 1) * 8;
    float acc[4][2][4];
    #pragma unroll
    for (int i = 0; i < 4; i++)
        #pragma unroll
        for (int j = 0; j < 2; j++)
            #pragma unroll
            for (int q = 0; q < 4; q++) acc[i][j][q] = 0.f;
    uint4 rah, ral, rbh, rbl;

    #define RLOAD(K0)                                                             \
    {                                                                             \
        const int k = (K0) + achk;                                                \
        if (k < Dn) {                                                             \
            rah = *(const uint4*)(g_hln_h + (size_t)(m0 + arow) * Dn + k);        \
            ral = *(const uint4*)(g_hln_l + (size_t)(m0 + arow) * Dn + k);        \
        } else {                                                                  \
            rah = *(const uint4*)(g_femb_h + (size_t)(m0 + arow) * DFEn + (k - Dn)); \
            ral = *(const uint4*)(g_femb_l + (size_t)(m0 + arow) * DFEn + (k - Dn)); \
        }                                                                         \
        if (tid < 128) {                                                          \
            rbh = *(const uint4*)(g_Wr1t_h + (size_t)(n0 + arow) * KINn + k);     \
            rbl = *(const uint4*)(g_Wr1t_l + (size_t)(n0 + arow) * KINn + k);     \
        }                                                                         \
    }
    #define RSTORE(BUF)                                                           \
    {                                                                             \
        *(uint4*)&Ah[BUF][arow][achk] = rah;                                      \
        *(uint4*)&Al[BUF][arow][achk] = ral;                                      \
        if (tid < 128) {                                                          \
            *(uint4*)&Bh[BUF][arow][achk] = rbh;                                  \
            *(uint4*)&Bl[BUF][arow][achk] = rbl;                                  \
        }                                                                         \
    }
    #define RCOMP(BUF)                                                            \
    {                                                                             \
        unsigned ah[4][4], al[4][4], bh[2][2], bl[2][2];                          \
        MMA_FRAG_A_S(ah, Ah, BUF)                                                 \
        MMA_FRAG_A_S(al, Al, BUF)                                                 \
        _Pragma("unroll")                                                         \
        for (int ni = 0; ni < 2; ni++) {                                          \
            const int nr = wn + ni * 8 + gid;                                     \
            bh[ni][0] = *(const unsigned*)&Bh[BUF][nr][2 * tig];                  \
            bh[ni][1] = *(const unsigned*)&Bh[BUF][nr][2 * tig + 8];              \
            bl[ni][0] = *(const unsigned*)&Bl[BUF][nr][2 * tig];                  \
            bl[ni][1] = *(const unsigned*)&Bl[BUF][nr][2 * tig + 8];              \
        }                                                                         \
        _Pragma("unroll")                                                         \
        for (int mi = 0; mi < 4; mi++)                                            \
            _Pragma("unroll")                                                     \
            for (int ni = 0; ni < 2; ni++) {                                      \
                mma_f16(acc[mi][ni], ah[mi], bh[ni]);                             \
                mma_f16(acc[mi][ni], ah[mi], bl[ni]);                             \
                mma_f16(acc[mi][ni], al[mi], bh[ni]);                             \
            }                                                                     \
    }

    const int nk = KINn / 16;  // 68
    RLOAD(0)
    RSTORE(0)
    __syncthreads();
    int buf = 0;
    for (int kt = 0; kt < nk; kt++) {
        if (kt + 1 < nk) RLOAD((kt + 1) * 16)
        RCOMP(buf)
        if (kt + 1 < nk) RSTORE(buf ^ 1)
        __syncthreads();
        buf ^= 1;
    }
    #undef RLOAD
    #undef RSTORE
    #undef RCOMP

    #pragma unroll
    for (int ni = 0; ni < 2; ni++) {
        const int c = n0 + wn + ni * 8 + 2 * tig;
        const float2 bb = *(const float2*)(bias + c);
        #pragma unroll
        for (int mi = 0; mi < 4; mi++) {
            const int r0 = m0 + wm + mi * 16 + gid;
            float2 o0, o1;
            o0.x = gelu_f(acc[mi][ni][0] + bb.x);
            o0.y = gelu_f(acc[mi][ni][1] + bb.y);
            o1.x = gelu_f(acc[mi][ni][2] + bb.x);
            o1.y = gelu_f(acc[mi][ni][3] + bb.y);
            *(float2*)(g_hr + (size_t)r0 * DRHn + c)       = o0;
            *(float2*)(g_hr + (size_t)(r0 + 8) * DRHn + c) = o1;
        }
    }
}

// ---------------- K3: logits (fp32), top-2 softmax, scatter + fused eemb ----------------
__global__ __launch_bounds__(256) void k_router_topk(
    const float* __restrict__ Wr2, const float* __restrict__ br2,
    const float* __restrict__ feat, const float* __restrict__ Wef,
    const float* __restrict__ bef, const int* __restrict__ expert_idx)
{
    __shared__ float w2s[DRHn * En];
    __shared__ float wefs[En * NEFn * DFEn];
    __shared__ float befs[En * DFEn];
    __shared__ int   eidx[En * NEFn];
    for (int i = threadIdx.x; i < DRHn * En; i += 256) w2s[i] = Wr2[i];
    for (int i = threadIdx.x; i < En * NEFn * DFEn; i += 256) wefs[i] = Wef[i];
    for (int i = threadIdx.x; i < En * DFEn; i += 256) befs[i] = bef[i];
    if (threadIdx.x < En * NEFn) eidx[threadIdx.x] = expert_idx[threadIdx.x];
    __syncthreads();

    const int w = threadIdx.x >> 5, l = threadIdx.x & 31;
    const int t = blockIdx.x * 8 + w;
    const float* hr = g_hr + (size_t)t * DRHn;

    float lg[En] = {};
    #pragma unroll
    for (int j = 0; j < DRHn / 32; j++) {
        const int k = l + 32 * j;
        const float hv = hr[k];
        #pragma unroll
        for (int e = 0; e < En; e++) lg[e] = fmaf(hv, w2s[k * En + e], lg[e]);
    }
    #pragma unroll
    for (int e = 0; e < En; e++) {
        #pragma unroll
        for (int o = 16; o > 0; o >>= 1) lg[e] += __shfl_xor_sync(0xffffffffu, lg[e], o);
    }
    int e1 = 0, e2 = -1;
    if (l == 0) {
        #pragma unroll
        for (int e = 0; e < En; e++) lg[e] += br2[e];
        float v1 = lg[0];
        #pragma unroll
        for (int e = 1; e < En; e++) if (lg[e] > v1) { v1 = lg[e]; e1 = e; }
        float v2 = -1e30f;
        #pragma unroll
        for (int e = 0; e < En; e++) if (e != e1 && lg[e] > v2) { v2 = lg[e]; e2 = e; }
        float z = expf(v2 - v1);
        float w1 = 1.0f / (1.0f + z);
        float w2 = z / (1.0f + z);
        g_toke[t * 2 + 0] = e1; g_toke[t * 2 + 1] = e2;
        g_tokw[t * 2 + 0] = w1; g_tokw[t * 2 + 1] = w2;
        int p1 = atomicAdd(&g_cnt[e1], 1); g_plist[e1 * Tn + p1] = t * 2;
        int p2 = atomicAdd(&g_cnt[e2], 1); g_plist[e2 * Tn + p2] = t * 2 + 1;
    }
    e1 = __shfl_sync(0xffffffffu, e1, 0);
    e2 = __shfl_sync(0xffffffffu, e2, 0);

    #pragma unroll
    for (int s = 0; s < 2; s++) {
        const int e = s ? e2 : e1;
        float fv[NEFn];
        #pragma unroll
        for (int f = 0; f < NEFn; f++)
            fv[f] = feat[(size_t)t * NCOLSn + eidx[e * NEFn + f]];
        #pragma unroll
        for (int half_d = 0; half_d < 2; half_d++) {
            const int d = l + half_d * 32;
            float acc = befs[e * DFEn + d];
            #pragma unroll
            for (int f = 0; f < NEFn; f++)
                acc = fmaf(fv[f], wefs[(e * NEFn + f) * DFEn + d], acc);
            g_eemb_h[(size_t)(t * 2 + s) * DFEn + d] = __float2half(acc);
        }
    }
}

// ================= expert GEMMs: cp.async 4-stage pipeline, per-expert launches =================
#define KT        32
#define STG       4
#define SUBBYTES  (128 * 24 * 2)          // 6144 B
#define STAGEB    (2 * SUBBYTES)          // 12288 B
#define EOFF_SROW 0
#define EOFF_A    1024
#define EOFF_B    (EOFF_A + STG * STAGEB) // 50176
#define ESMEM     (EOFF_B + STG * STAGEB) // 99328

template<bool G1>
__global__ __launch_bounds__(256, 2) void k_exp_gemm_p(
    const __half* __restrict__ Wt, const float* __restrict__ bias, int e)
{
    constexpr int KD  = G1 ? KINn : DEHn;   // 1088 / 2048
    constexpr int NKt = KD / KT;            // 34 / 64
    constexpr int DST = G1 ? DEHn : Dn;
    const int cnt = g_cnt[e];
    const int m0 = blockIdx.x * 128;
    if (m0 >= cnt) return;
    const int n0 = blockIdx.y * 128;

    extern __shared__ char smem[];
    const uint32_t sb = smem_u32(smem);
    int* srow = (int*)(smem + EOFF_SROW);

    const int tid = threadIdx.x;
    const int warp = tid >> 5, lane = tid & 31;
    const int wm = (warp >> 2) * 64, wn = (warp & 3) * 32;
    const int gid = lane >> 2, tig = lane & 3;
    const int arow = tid >> 1;
    float acc[4][4][4];
    #pragma unroll
    for (int i = 0; i < 4; i++)
        #pragma unroll
        for (int j = 0; j < 4; j++)
            #pragma unroll
            for (int q = 0; q < 4; q++) acc[i][j][q] = 0.f;

    if (tid < 128) {
        int m = m0 + tid;
        srow[tid] = (m < cnt) ? g_plist[e * Tn + m] : -1;
    }
    __syncthreads();

    const int lrow = arow;           // tid >> 1
    const int lsel = (tid & 1);
    const int lslot = srow[lrow];
    const __half* Wte = Wt + (size_t)e * KD * DST;

    #define APTR(slot, k)                                                          \
        (G1 ? (((k) < Dn) ? (g_hln_h + (size_t)(((slot) < 0 ? 0 : (slot)) >> 1) * Dn + (k)) \
                          : (g_eemb_h + (size_t)((slot) < 0 ? 0 : (slot)) * DFEn + ((k) - Dn))) \
            : (g_hh_h + (size_t)((slot) < 0 ? 0 : (slot)) * DEHn + (k)))

    #define EISSUE(KTI)                                                            \
    {                                                                              \
        const int k0 = (KTI) * KT;                                                 \
        const int st = (KTI) % STG;                                                \
        const uint32_t ab = sb + EOFF_A + st * STAGEB;                             \
        const uint32_t bb = sb + EOFF_B + st * STAGEB;                             \
        _Pragma("unroll")                                                          \
        for (int s = 0; s < 2; s++) {                                              \
            const int k = k0 + s * 16 + lsel * 8;                                  \
            const uint32_t doff = (uint32_t)(s * SUBBYTES + lrow * 48 + lsel * 16);\
            cp_async16(ab + doff, APTR(lslot, k), lslot >= 0 ? 16 : 0);            \
            cp_async16(bb + doff, Wte + (size_t)(n0 + lrow) * KD + k, 16);         \
        }                                                                          \
    }

    #define ECOMP(ST)                                                              \
    {                                                                              \
        _Pragma("unroll")                                                          \
        for (int s = 0; s < 2; s++) {                                              \
            const __half (*AP)[24] = (const __half(*)[24])                         \
                (smem + EOFF_A + (ST) * STAGEB + s * SUBBYTES);                    \
            const __half (*BP)[24] = (const __half(*)[24])                         \
                (smem + EOFF_B + (ST) * STAGEB + s * SUBBYTES);                    \
            unsigned a[4][4], b[4][2];                                             \
            MMA_FRAG_A_P(a, AP)                                                    \
            MMA_FRAG_B_P(b, BP)                                                    \
            _Pragma("unroll")                                                      \
            for (int mi = 0; mi < 4; mi++)                                         \
                _Pragma("unroll")                                                  \
                for (int ni = 0; ni < 4; ni++)                                     \
                    mma_f16(acc[mi][ni], a[mi], b[ni]);                            \
        }                                                                          \
    }

    EISSUE(0)
    asm volatile("cp.async.commit_group;" ::: "memory");
    EISSUE(1)
    asm volatile("cp.async.commit_group;" ::: "memory");
    EISSUE(2)
    asm volatile("cp.async.commit_group;" ::: "memory");

    for (int kt = 0; kt < NKt; kt++) {
        asm volatile("cp.async.wait_group 2;" ::: "memory");
        __syncthreads();
        if (kt + 3 < NKt) EISSUE(kt + 3)
        asm volatile("cp.async.commit_group;" ::: "memory");
        ECOMP(kt % STG)
    }
    #undef APTR
    #undef EISSUE
    #undef ECOMP

    // epilogue
    #pragma unroll
    for (int ni = 0; ni < 4; ni++) {
        const int c = n0 + wn + ni * 8 + 2 * tig;
        const float2 bb = *(const float2*)(bias + (size_t)e * DST + c);
        #pragma unroll
        for (int mi = 0; mi < 4; mi++) {
            const int r0 = wm + mi * 16 + gid;
            const int s0 = srow[r0], s1 = srow[r0 + 8];
            if (G1) {
                if (s0 >= 0) {
                    __half2 o = __floats2half2_rn(gelu_f(acc[mi][ni][0] + bb.x),
                                                  gelu_f(acc[mi][ni][1] + bb.y));
                    *(__half2*)(g_hh_h + (size_t)s0 * DEHn + c) = o;
                }
                if (s1 >= 0) {
                    __half2 o = __floats2half2_rn(gelu_f(acc[mi][ni][2] + bb.x),
                                                  gelu_f(acc[mi][ni][3] + bb.y));
                    *(__half2*)(g_hh_h + (size_t)s1 * DEHn + c) = o;
                }
            } else {
                if (s0 >= 0) {
                    __half2 o = __floats2half2_rn(acc[mi][ni][0] + bb.x,
                                                  acc[mi][ni][1] + bb.y);
                    *(__half2*)(g_eo_h + (size_t)s0 * Dn + c) = o;
                }
                if (s1 >= 0) {
                    __half2 o = __floats2half2_rn(acc[mi][ni][2] + bb.x,
                                                  acc[mi][ni][3] + bb.y);
                    *(__half2*)(g_eo_h + (size_t)s1 * Dn + c) = o;
                }
            }
        }
    }
}

// ---------------- K6: weighted combine + residual (fp16 eo) ----------------
__global__ __launch_bounds__(256) void k_combine(
    const float* __restrict__ h, float* __restrict__ out)
{
    const int t = blockIdx.x;
    const int i = threadIdx.x;
    const float w0 = g_tokw[t * 2 + 0];
    const float w1 = g_tokw[t * 2 + 1];
    const float4 hv = ((const float4*)(h + (size_t)t * Dn))[i];
    const __half2* pa = (const __half2*)(g_eo_h + (size_t)(t * 2 + 0) * Dn);
    const __half2* pb = (const __half2*)(g_eo_h + (size_t)(t * 2 + 1) * Dn);
    float2 a0 = __half22float2(pa[i * 2]),     a1 = __half22float2(pa[i * 2 + 1]);
    float2 b0 = __half22float2(pb[i * 2]),     b1 = __half22float2(pb[i * 2 + 1]);
    float4 o;
    o.x = hv.x + w0 * a0.x + w1 * b0.x;
    o.y = hv.y + w0 * a0.y + w1 * b0.y;
    o.z = hv.z + w0 * a1.x + w1 * b1.x;
    o.w = hv.w + w0 * a1.y + w1 * b1.y;
    ((float4*)(out + (size_t)t * Dn))[i] = o;
}

// ---------------- launch ----------------
extern "C" void kernel_launch(void* const* d_in, const int* in_sizes, int n_in,
                              void* d_out, int out_size)
{
    const float* h         = (const float*)d_in[0];
    const float* feat      = (const float*)d_in[1];
    const float* ln_g      = (const float*)d_in[2];
    const float* ln_b      = (const float*)d_in[3];
    const float* Wsf       = (const float*)d_in[4];
    const float* bsf       = (const float*)d_in[5];
    const float* Wr1       = (const float*)d_in[6];
    const float* br1       = (const float*)d_in[7];
    const float* Wr2       = (const float*)d_in[8];
    const float* br2       = (const float*)d_in[9];
    const float* Wef       = (const float*)d_in[10];
    const float* bef       = (const float*)d_in[11];
    const float* We1       = (const float*)d_in[12];
    const float* be1       = (const float*)d_in[13];
    const float* We2       = (const float*)d_in[14];
    const float* be2       = (const float*)d_in[15];
    const int*   stage_idx = (const int*)d_in[16];
    const int*   expert_idx= (const int*)d_in[17];
    float* out = (float*)d_out;

    __half* We1t; cudaGetSymbolAddress((void**)&We1t, g_We1t_h);
    __half* We2t; cudaGetSymbolAddress((void**)&We2t, g_We2t_h);
    __half* Wr1th; cudaGetSymbolAddress((void**)&Wr1th, g_Wr1t_h);
    __half* Wr1tl; cudaGetSymbolAddress((void**)&Wr1tl, g_Wr1t_l);

    cudaFuncSetAttribute(k_exp_gemm_p<true>,
                         cudaFuncAttributeMaxDynamicSharedMemorySize, ESMEM);
    cudaFuncSetAttribute(k_exp_gemm_p<false>,
                         cudaFuncAttributeMaxDynamicSharedMemorySize, ESMEM);

    static cudaStream_t sW = nullptr;
    static cudaEvent_t evRoot = nullptr, evHl = nullptr, evW1 = nullptr;
    static cudaEvent_t ev1[En], ev2Last = nullptr;
    if (!sW) {
        cudaStreamCreateWithFlags(&sW, cudaStreamNonBlocking);
        cudaEventCreateWithFlags(&evRoot, cudaEventDisableTiming);
        cudaEventCreateWithFlags(&evHl,   cudaEventDisableTiming);
        cudaEventCreateWithFlags(&evW1,   cudaEventDisableTiming);
        cudaEventCreateWithFlags(&ev2Last, cudaEventDisableTiming);
        for (int e = 0; e < En; e++)
            cudaEventCreateWithFlags(&ev1[e], cudaEventDisableTiming);
    }

    // fork: weight transposes on sW, overlapped with token path
    cudaEventRecord(evRoot, 0);
    cudaStreamWaitEvent(sW, evRoot, 0);
    k_transpose_hl<<<dim3(DRHn / 32, KINn / 32, 1), dim3(32, 8), 0, sW>>>(
        Wr1, Wr1th, Wr1tl, KINn, DRHn);
    cudaEventRecord(evHl, sW);
    k_transpose_h<<<dim3(DEHn / 32, KINn / 32, En), dim3(32, 8), 0, sW>>>(
        We1, We1t, KINn, DEHn);
    cudaEventRecord(evW1, sW);
    k_transpose_h<<<dim3(Dn / 32, DEHn / 32, En), dim3(32, 8), 0, sW>>>(
        We2, We2t, DEHn, Dn);
    // (gemm2 runs on sW, in-order after this transpose)

    // token path on default stream
    k_ln<<<Tn, 256>>>(h, feat, ln_g, ln_b, Wsf, bsf, stage_idx);
    cudaStreamWaitEvent(0, evHl, 0);
    k_router_gemm_split<<<dim3(DRHn / 64, Tn / 128), 256>>>(br1);
    k_router_topk<<<Tn / 8, 256>>>(Wr2, br2, feat, Wef, bef, expert_idx);
    cudaStreamWaitEvent(0, evW1, 0);

    // per-expert paired GEMMs: gemm1(e) on stream 0, gemm2(e) on sW after ev1[e].
    // gemm2(e-1) fills SM slots while gemm1(e) runs.
    for (int e = 0; e < En; e++) {
        k_exp_gemm_p<true><<<dim3(Tn / 128, DEHn / 128, 1), 256, ESMEM>>>(We1t, be1, e);
        cudaEventRecord(ev1[e], 0);
        cudaStreamWaitEvent(sW, ev1[e], 0);
        k_exp_gemm_p<false><<<dim3(Tn / 128, Dn / 128, 1), 256, ESMEM, sW>>>(We2t, be2, e);
    }
    cudaEventRecord(ev2Last, sW);
    cudaStreamWaitEvent(0, ev2Last, 0);
    k_combine<<<Tn, 256>>>(h, out);
}

// round 13
// speedup vs baseline: 1.3112x; 1.3112x over previous
#include <cuda_runtime.h>
#include <cuda_fp16.h>
#include <math.h>
#include <stdint.h>

// ---------------- problem constants ----------------
#define Tn    8192          // B*S tokens
#define Dn    1024          // d_model
#define NCOLSn 32
#define FSn   16
#define NEFn  8
#define En    8
#define DFEn  64
#define DRHn  256
#define DEHn  2048
#define KINn  (Dn + DFEn)   // 1088
#define EPSf  1e-5f

// ---------------- scratch ----------------
__device__ __half g_hln_h [Tn * Dn];
__device__ __half g_hln_l [Tn * Dn];
__device__ __half g_femb_h[Tn * DFEn];
__device__ __half g_femb_l[Tn * DFEn];
__device__ float  g_hr    [Tn * DRHn];
__device__ int    g_cnt   [En];
__device__ int    g_plist [En * Tn];
__device__ int    g_toke  [Tn * 2];
__device__ float  g_tokw  [Tn * 2];
__device__ __half g_eemb_h[Tn * 2 * DFEn];
__device__ __half g_hh_h  [Tn * 2 * DEHn];
__device__ __half g_eo_h  [Tn * 2 * Dn];
__device__ __half g_We1t_h[En * (size_t)KINn * DEHn]; // [e][n][k]
__device__ __half g_We2t_h[En * (size_t)DEHn * Dn];   // [e][n][k]
__device__ __half g_Wr1t_h[(size_t)KINn * DRHn];
__device__ __half g_Wr1t_l[(size_t)KINn * DRHn];

__device__ __forceinline__ float gelu_f(float x) {
    float x3 = x * x * x;
    return 0.5f * x * (1.0f + tanhf(0.7978845608028654f * (x + 0.044715f * x3)));
}

__device__ __forceinline__ void mma_f16(float c[4], const unsigned a[4], const unsigned b[2]) {
    asm volatile(
        "mma.sync.aligned.m16n8k16.row.col.f32.f16.f16.f32 "
        "{%0,%1,%2,%3}, {%4,%5,%6,%7}, {%8,%9}, {%0,%1,%2,%3};"
        : "+f"(c[0]), "+f"(c[1]), "+f"(c[2]), "+f"(c[3])
        : "r"(a[0]), "r"(a[1]), "r"(a[2]), "r"(a[3]), "r"(b[0]), "r"(b[1]));
}

__device__ __forceinline__ uint32_t smem_u32(const void* p) {
    uint32_t a;
    asm("{ .reg .u64 t; cvta.to.shared.u64 t, %1; cvt.u32.u64 %0, t; }" : "=r"(a) : "l"(p));
    return a;
}
__device__ __forceinline__ void cp_async16(uint32_t d, const void* s, int sz) {
    asm volatile("cp.async.cg.shared.global [%0], [%1], 16, %2;"
                 :: "r"(d), "l"(s), "r"(sz) : "memory");
}

// ---------------- K0a: weight transpose+cvt  W[e][K][N] f32 -> Wt[e][N][K] f16 ----------------
__global__ __launch_bounds__(256) void k_transpose_h(
    const float* __restrict__ W, __half* __restrict__ Wt, int K, int N)
{
    __shared__ float tile[32][33];
    const int e = blockIdx.z;
    const float* Wp  = W  + (size_t)e * K * N;
    __half*      Wtp = Wt + (size_t)e * K * N;
    int x = blockIdx.x * 32 + threadIdx.x;   // n
    int y = blockIdx.y * 32 + threadIdx.y;   // k
    #pragma unroll
    for (int i = 0; i < 32; i += 8)
        tile[threadIdx.y + i][threadIdx.x] = Wp[(size_t)(y + i) * N + x];
    __syncthreads();
    x = blockIdx.y * 32 + threadIdx.x;       // k
    y = blockIdx.x * 32 + threadIdx.y;       // n
    #pragma unroll
    for (int i = 0; i < 32; i += 8)
        Wtp[(size_t)(y + i) * K + x] = __float2half(tile[threadIdx.x][threadIdx.y + i]);
}

// ---------------- K0b: transpose with hi/lo split (router W1) ----------------
__global__ __launch_bounds__(256) void k_transpose_hl(
    const float* __restrict__ W, __half* __restrict__ Wth, __half* __restrict__ Wtl,
    int K, int N)
{
    __shared__ float tile[32][33];
    int x = blockIdx.x * 32 + threadIdx.x;   // n
    int y = blockIdx.y * 32 + threadIdx.y;   // k
    #pragma unroll
    for (int i = 0; i < 32; i += 8)
        tile[threadIdx.y + i][threadIdx.x] = W[(size_t)(y + i) * N + x];
    __syncthreads();
    x = blockIdx.y * 32 + threadIdx.x;       // k
    y = blockIdx.x * 32 + threadIdx.y;       // n
    #pragma unroll
    for (int i = 0; i < 32; i += 8) {
        float v = tile[threadIdx.x][threadIdx.y + i];
        __half hi = __float2half(v);
        __half lo = __float2half(v - __half2float(hi));
        Wth[(size_t)(y + i) * K + x] = hi;
        Wtl[(size_t)(y + i) * K + x] = lo;
    }
}

// ---------------- K1: layernorm + stage-feature embedding (+ zero cnt) ----------------
__global__ __launch_bounds__(256) void k_ln(
    const float* __restrict__ h, const float* __restrict__ feat,
    const float* __restrict__ ln_g, const float* __restrict__ ln_b,
    const float* __restrict__ Wsf, const float* __restrict__ bsf,
    const int* __restrict__ stage_idx)
{
    const int t = blockIdx.x;
    const int tid = threadIdx.x;
    if (blockIdx.x == 0 && tid < En) g_cnt[tid] = 0;
    const float4 xv = ((const float4*)(h + (size_t)t * Dn))[tid];

    float s  = xv.x + xv.y + xv.z + xv.w;
    float s2 = xv.x * xv.x + xv.y * xv.y + xv.z * xv.z + xv.w * xv.w;
    #pragma unroll
    for (int o = 16; o > 0; o >>= 1) {
        s  += __shfl_xor_sync(0xffffffffu, s,  o);
        s2 += __shfl_xor_sync(0xffffffffu, s2, o);
    }
    __shared__ float rs[8], rs2[8], stats[2];
    if ((tid & 31) == 0) { rs[tid >> 5] = s; rs2[tid >> 5] = s2; }
    __syncthreads();
    if (tid == 0) {
        float a = 0.f, a2 = 0.f;
        #pragma unroll
        for (int i = 0; i < 8; i++) { a += rs[i]; a2 += rs2[i]; }
        float m = a * (1.0f / Dn);
        stats[0] = m;
        stats[1] = rsqrtf(a2 * (1.0f / Dn) - m * m + EPSf);
    }
    __shared__ float sf[FSn];
    if (tid < FSn) sf[tid] = feat[(size_t)t * NCOLSn + stage_idx[tid]];
    __syncthreads();

    const float m = stats[0], r = stats[1];
    const float4 gv = ((const float4*)ln_g)[tid];
    const float4 bv = ((const float4*)ln_b)[tid];
    float o[4];
    o[0] = (xv.x - m) * r * gv.x + bv.x;
    o[1] = (xv.y - m) * r * gv.y + bv.y;
    o[2] = (xv.z - m) * r * gv.z + bv.z;
    o[3] = (xv.w - m) * r * gv.w + bv.w;
    __half2* dh = (__half2*)(g_hln_h + (size_t)t * Dn);
    __half2* dl = (__half2*)(g_hln_l + (size_t)t * Dn);
    #pragma unroll
    for (int q = 0; q < 2; q++) {
        __half2 hi = __floats2half2_rn(o[2 * q], o[2 * q + 1]);
        float2 hif = __half22float2(hi);
        __half2 lo = __floats2half2_rn(o[2 * q] - hif.x, o[2 * q + 1] - hif.y);
        dh[tid * 2 + q] = hi;
        dl[tid * 2 + q] = lo;
    }

    if (tid < DFEn) {
        float acc = bsf[tid];
        #pragma unroll
        for (int f = 0; f < FSn; f++) acc = fmaf(sf[f], Wsf[f * DFEn + tid], acc);
        __half hi = __float2half(acc);
        g_femb_h[(size_t)t * DFEn + tid] = hi;
        g_femb_l[(size_t)t * DFEn + tid] = __float2half(acc - __half2float(hi));
    }
}

// ================= shared mma fragment macros (R6 layout, conflict-free LDS.32) =================
#define MMA_FRAG_A_S(dst, SM, BUF)                                                \
    _Pragma("unroll")                                                             \
    for (int mi = 0; mi < 4; mi++) {                                              \
        const int r0 = wm + mi * 16 + gid;                                        \
        dst[mi][0] = *(const unsigned*)&SM[BUF][r0][2 * tig];                     \
        dst[mi][1] = *(const unsigned*)&SM[BUF][r0 + 8][2 * tig];                 \
        dst[mi][2] = *(const unsigned*)&SM[BUF][r0][2 * tig + 8];                 \
        dst[mi][3] = *(const unsigned*)&SM[BUF][r0 + 8][2 * tig + 8];             \
    }

#define MMA_FRAG_A_P(dst, AP)                                                     \
    _Pragma("unroll")                                                             \
    for (int mi = 0; mi < 4; mi++) {                                              \
        const int r0 = wm + mi * 16 + gid;                                        \
        dst[mi][0] = *(const unsigned*)&AP[r0][2 * tig];                          \
        dst[mi][1] = *(const unsigned*)&AP[r0 + 8][2 * tig];                      \
        dst[mi][2] = *(const unsigned*)&AP[r0][2 * tig + 8];                      \
        dst[mi][3] = *(const unsigned*)&AP[r0 + 8][2 * tig + 8];                  \
    }
#define MMA_FRAG_B_P(dst, BP)                                                     \
    _Pragma("unroll")                                                             \
    for (int ni = 0; ni < 4; ni++) {                                              \
        const int nr = wn + ni * 8 + gid;                                         \
        dst[ni][0] = *(const unsigned*)&BP[nr][2 * tig];                          \
        dst[ni][1] = *(const unsigned*)&BP[nr][2 * tig + 8];                      \
    }

// ---------------- router GEMM1 (split-fp16, 128M x 64N tiles, 2 CTA/SM) ----------------
__global__ __launch_bounds__(256, 2) void k_router_gemm_split(const float* __restrict__ bias)
{
    __shared__ __half Ah[2][128][24];
    __shared__ __half Al[2][128][24];
    __shared__ __half Bh[2][64][24];
    __shared__ __half Bl[2][64][24];
    const int m0 = blockIdx.y * 128, n0 = blockIdx.x * 64;
    const int tid = threadIdx.x;
    const int warp = tid >> 5, lane = tid & 31;
    const int wm = (warp >> 2) * 64, wn = (warp & 3) * 16;
    const int gid = lane >> 2, tig = lane & 3;
    const int arow = tid >> 1, achk = (tid & 1) * 8;
    float acc[4][2][4];
    #pragma unroll
    for (int i = 0; i < 4; i++)
        #pragma unroll
        for (int j = 0; j < 2; j++)
            #pragma unroll
            for (int q = 0; q < 4; q++) acc[i][j][q] = 0.f;
    uint4 rah, ral, rbh, rbl;

    #define RLOAD(K0)                                                             \
    {                                                                             \
        const int k = (K0) + achk;                                                \
        if (k < Dn) {                                                             \
            rah = *(const uint4*)(g_hln_h + (size_t)(m0 + arow) * Dn + k);        \
            ral = *(const uint4*)(g_hln_l + (size_t)(m0 + arow) * Dn + k);        \
        } else {                                                                  \
            rah = *(const uint4*)(g_femb_h + (size_t)(m0 + arow) * DFEn + (k - Dn)); \
            ral = *(const uint4*)(g_femb_l + (size_t)(m0 + arow) * DFEn + (k - Dn)); \
        }                                                                         \
        if (tid < 128) {                                                          \
            rbh = *(const uint4*)(g_Wr1t_h + (size_t)(n0 + arow) * KINn + k);     \
            rbl = *(const uint4*)(g_Wr1t_l + (size_t)(n0 + arow) * KINn + k);     \
        }                                                                         \
    }
    #define RSTORE(BUF)                                                           \
    {                                                                             \
        *(uint4*)&Ah[BUF][arow][achk] = rah;                                      \
        *(uint4*)&Al[BUF][arow][achk] = ral;                                      \
        if (tid < 128) {                                                          \
            *(uint4*)&Bh[BUF][arow][achk] = rbh;                                  \
            *(uint4*)&Bl[BUF][arow][achk] = rbl;                                  \
        }                                                                         \
    }
    #define RCOMP(BUF)                                                            \
    {                                                                             \
        unsigned ah[4][4], al[4][4], bh[2][2], bl[2][2];                          \
        MMA_FRAG_A_S(ah, Ah, BUF)                                                 \
        MMA_FRAG_A_S(al, Al, BUF)                                                 \
        _Pragma("unroll")                                                         \
        for (int ni = 0; ni < 2; ni++) {                                          \
            const int nr = wn + ni * 8 + gid;                                     \
            bh[ni][0] = *(const unsigned*)&Bh[BUF][nr][2 * tig];                  \
            bh[ni][1] = *(const unsigned*)&Bh[BUF][nr][2 * tig + 8];              \
            bl[ni][0] = *(const unsigned*)&Bl[BUF][nr][2 * tig];                  \
            bl[ni][1] = *(const unsigned*)&Bl[BUF][nr][2 * tig + 8];              \
        }                                                                         \
        _Pragma("unroll")                                                         \
        for (int mi = 0; mi < 4; mi++)                                            \
            _Pragma("unroll")                                                     \
            for (int ni = 0; ni < 2; ni++) {                                      \
                mma_f16(acc[mi][ni], ah[mi], bh[ni]);                             \
                mma_f16(acc[mi][ni], ah[mi], bl[ni]);                             \
                mma_f16(acc[mi][ni], al[mi], bh[ni]);                             \
            }                                                                     \
    }

    const int nk = KINn / 16;  // 68
    RLOAD(0)
    RSTORE(0)
    __syncthreads();
    int buf = 0;
    for (int kt = 0; kt < nk; kt++) {
        if (kt + 1 < nk) RLOAD((kt + 1) * 16)
        RCOMP(buf)
        if (kt + 1 < nk) RSTORE(buf ^ 1)
        __syncthreads();
        buf ^= 1;
    }
    #undef RLOAD
    #undef RSTORE
    #undef RCOMP

    #pragma unroll
    for (int ni = 0; ni < 2; ni++) {
        const int c = n0 + wn + ni * 8 + 2 * tig;
        const float2 bb = *(const float2*)(bias + c);
        #pragma unroll
        for (int mi = 0; mi < 4; mi++) {
            const int r0 = m0 + wm + mi * 16 + gid;
            float2 o0, o1;
            o0.x = gelu_f(acc[mi][ni][0] + bb.x);
            o0.y = gelu_f(acc[mi][ni][1] + bb.y);
            o1.x = gelu_f(acc[mi][ni][2] + bb.x);
            o1.y = gelu_f(acc[mi][ni][3] + bb.y);
            *(float2*)(g_hr + (size_t)r0 * DRHn + c)       = o0;
            *(float2*)(g_hr + (size_t)(r0 + 8) * DRHn + c) = o1;
        }
    }
}

// ---------------- K3: logits (fp32), top-2 softmax, scatter + fused eemb ----------------
__global__ __launch_bounds__(256) void k_router_topk(
    const float* __restrict__ Wr2, const float* __restrict__ br2,
    const float* __restrict__ feat, const float* __restrict__ Wef,
    const float* __restrict__ bef, const int* __restrict__ expert_idx)
{
    __shared__ float w2s[DRHn * En];
    __shared__ float wefs[En * NEFn * DFEn];
    __shared__ float befs[En * DFEn];
    __shared__ int   eidx[En * NEFn];
    for (int i = threadIdx.x; i < DRHn * En; i += 256) w2s[i] = Wr2[i];
    for (int i = threadIdx.x; i < En * NEFn * DFEn; i += 256) wefs[i] = Wef[i];
    for (int i = threadIdx.x; i < En * DFEn; i += 256) befs[i] = bef[i];
    if (threadIdx.x < En * NEFn) eidx[threadIdx.x] = expert_idx[threadIdx.x];
    __syncthreads();

    const int w = threadIdx.x >> 5, l = threadIdx.x & 31;
    const int t = blockIdx.x * 8 + w;
    const float* hr = g_hr + (size_t)t * DRHn;

    float lg[En] = {};
    #pragma unroll
    for (int j = 0; j < DRHn / 32; j++) {
        const int k = l + 32 * j;
        const float hv = hr[k];
        #pragma unroll
        for (int e = 0; e < En; e++) lg[e] = fmaf(hv, w2s[k * En + e], lg[e]);
    }
    #pragma unroll
    for (int e = 0; e < En; e++) {
        #pragma unroll
        for (int o = 16; o > 0; o >>= 1) lg[e] += __shfl_xor_sync(0xffffffffu, lg[e], o);
    }
    int e1 = 0, e2 = -1;
    if (l == 0) {
        #pragma unroll
        for (int e = 0; e < En; e++) lg[e] += br2[e];
        float v1 = lg[0];
        #pragma unroll
        for (int e = 1; e < En; e++) if (lg[e] > v1) { v1 = lg[e]; e1 = e; }
        float v2 = -1e30f;
        #pragma unroll
        for (int e = 0; e < En; e++) if (e != e1 && lg[e] > v2) { v2 = lg[e]; e2 = e; }
        float z = expf(v2 - v1);
        float w1 = 1.0f / (1.0f + z);
        float w2 = z / (1.0f + z);
        g_toke[t * 2 + 0] = e1; g_toke[t * 2 + 1] = e2;
        g_tokw[t * 2 + 0] = w1; g_tokw[t * 2 + 1] = w2;
        int p1 = atomicAdd(&g_cnt[e1], 1); g_plist[e1 * Tn + p1] = t * 2;
        int p2 = atomicAdd(&g_cnt[e2], 1); g_plist[e2 * Tn + p2] = t * 2 + 1;
    }
    e1 = __shfl_sync(0xffffffffu, e1, 0);
    e2 = __shfl_sync(0xffffffffu, e2, 0);

    #pragma unroll
    for (int s = 0; s < 2; s++) {
        const int e = s ? e2 : e1;
        float fv[NEFn];
        #pragma unroll
        for (int f = 0; f < NEFn; f++)
            fv[f] = feat[(size_t)t * NCOLSn + eidx[e * NEFn + f]];
        #pragma unroll
        for (int half_d = 0; half_d < 2; half_d++) {
            const int d = l + half_d * 32;
            float acc = befs[e * DFEn + d];
            #pragma unroll
            for (int f = 0; f < NEFn; f++)
                acc = fmaf(fv[f], wefs[(e * NEFn + f) * DFEn + d], acc);
            g_eemb_h[(size_t)(t * 2 + s) * DFEn + d] = __float2half(acc);
        }
    }
}

// ================= expert GEMMs: cp.async 4-stage pipeline, R6 fragment layout =================
#define KT        32
#define STG       4
#define SUBBYTES  (128 * 24 * 2)          // 6144 B
#define STAGEB    (2 * SUBBYTES)          // 12288 B
#define EOFF_SROW 0
#define EOFF_A    1024
#define EOFF_B    (EOFF_A + STG * STAGEB) // 50176
#define ESMEM     (EOFF_B + STG * STAGEB) // 99328

template<bool G1>
__global__ __launch_bounds__(256, 2) void k_exp_gemm_p(
    const __half* __restrict__ Wt, const float* __restrict__ bias)
{
    constexpr int KD  = G1 ? KINn : DEHn;   // 1088 / 2048
    constexpr int NKt = KD / KT;            // 34 / 64
    constexpr int DST = G1 ? DEHn : Dn;
    const int e = blockIdx.z;
    const int cnt = g_cnt[e];
    const int m0 = blockIdx.x * 128;
    if (m0 >= cnt) return;
    const int n0 = blockIdx.y * 128;

    extern __shared__ char smem[];
    const uint32_t sb = smem_u32(smem);
    int* srow = (int*)(smem + EOFF_SROW);

    const int tid = threadIdx.x;
    const int warp = tid >> 5, lane = tid & 31;
    const int wm = (warp >> 2) * 64, wn = (warp & 3) * 32;
    const int gid = lane >> 2, tig = lane & 3;
    const int arow = tid >> 1;
    float acc[4][4][4];
    #pragma unroll
    for (int i = 0; i < 4; i++)
        #pragma unroll
        for (int j = 0; j < 4; j++)
            #pragma unroll
            for (int q = 0; q < 4; q++) acc[i][j][q] = 0.f;

    if (tid < 128) {
        int m = m0 + tid;
        srow[tid] = (m < cnt) ? g_plist[e * Tn + m] : -1;
    }
    __syncthreads();

    const int lrow = arow;           // tid >> 1
    const int lsel = (tid & 1);
    const int lslot = srow[lrow];
    const __half* Wte = Wt + (size_t)e * KD * DST;

    #define APTR(slot, k)                                                          \
        (G1 ? (((k) < Dn) ? (g_hln_h + (size_t)(((slot) < 0 ? 0 : (slot)) >> 1) * Dn + (k)) \
                          : (g_eemb_h + (size_t)((slot) < 0 ? 0 : (slot)) * DFEn + ((k) - Dn))) \
            : (g_hh_h + (size_t)((slot) < 0 ? 0 : (slot)) * DEHn + (k)))

    #define EISSUE(KTI)                                                            \
    {                                                                              \
        const int k0 = (KTI) * KT;                                                 \
        const int st = (KTI) % STG;                                                \
        const uint32_t ab = sb + EOFF_A + st * STAGEB;                             \
        const uint32_t bb = sb + EOFF_B + st * STAGEB;                             \
        _Pragma("unroll")                                                          \
        for (int s = 0; s < 2; s++) {                                              \
            const int k = k0 + s * 16 + lsel * 8;                                  \
            const uint32_t doff = (uint32_t)(s * SUBBYTES + lrow * 48 + lsel * 16);\
            cp_async16(ab + doff, APTR(lslot, k), lslot >= 0 ? 16 : 0);            \
            cp_async16(bb + doff, Wte + (size_t)(n0 + lrow) * KD + k, 16);         \
        }                                                                          \
    }

    #define ECOMP(ST)                                                              \
    {                                                                              \
        _Pragma("unroll")                                                          \
        for (int s = 0; s < 2; s++) {                                              \
            const __half (*AP)[24] = (const __half(*)[24])                         \
                (smem + EOFF_A + (ST) * STAGEB + s * SUBBYTES);                    \
            const __half (*BP)[24] = (const __half(*)[24])                         \
                (smem + EOFF_B + (ST) * STAGEB + s * SUBBYTES);                    \
            unsigned a[4][4], b[4][2];                                             \
            MMA_FRAG_A_P(a, AP)                                                    \
            MMA_FRAG_B_P(b, BP)                                                    \
            _Pragma("unroll")                                                      \
            for (int mi = 0; mi < 4; mi++)                                         \
                _Pragma("unroll")                                                  \
                for (int ni = 0; ni < 4; ni++)                                     \
                    mma_f16(acc[mi][ni], a[mi], b[ni]);                            \
        }                                                                          \
    }

    EISSUE(0)
    asm volatile("cp.async.commit_group;" ::: "memory");
    EISSUE(1)
    asm volatile("cp.async.commit_group;" ::: "memory");
    EISSUE(2)
    asm volatile("cp.async.commit_group;" ::: "memory");

    #pragma unroll 4
    for (int kt = 0; kt < NKt; kt++) {
        asm volatile("cp.async.wait_group 2;" ::: "memory");
        __syncthreads();
        if (kt + 3 < NKt) EISSUE(kt + 3)
        asm volatile("cp.async.commit_group;" ::: "memory");
        ECOMP(kt % STG)
    }
    #undef APTR
    #undef EISSUE
    #undef ECOMP

    // epilogue
    #pragma unroll
    for (int ni = 0; ni < 4; ni++) {
        const int c = n0 + wn + ni * 8 + 2 * tig;
        const float2 bb = *(const float2*)(bias + (size_t)e * DST + c);
        #pragma unroll
        for (int mi = 0; mi < 4; mi++) {
            const int r0 = wm + mi * 16 + gid;
            const int s0 = srow[r0], s1 = srow[r0 + 8];
            if (G1) {
                if (s0 >= 0) {
                    __half2 o = __floats2half2_rn(gelu_f(acc[mi][ni][0] + bb.x),
                                                  gelu_f(acc[mi][ni][1] + bb.y));
                    *(__half2*)(g_hh_h + (size_t)s0 * DEHn + c) = o;
                }
                if (s1 >= 0) {
                    __half2 o = __floats2half2_rn(gelu_f(acc[mi][ni][2] + bb.x),
                                                  gelu_f(acc[mi][ni][3] + bb.y));
                    *(__half2*)(g_hh_h + (size_t)s1 * DEHn + c) = o;
                }
            } else {
                if (s0 >= 0) {
                    __half2 o = __floats2half2_rn(acc[mi][ni][0] + bb.x,
                                                  acc[mi][ni][1] + bb.y);
                    *(__half2*)(g_eo_h + (size_t)s0 * Dn + c) = o;
                }
                if (s1 >= 0) {
                    __half2 o = __floats2half2_rn(acc[mi][ni][2] + bb.x,
                                                  acc[mi][ni][3] + bb.y);
                    *(__half2*)(g_eo_h + (size_t)s1 * Dn + c) = o;
                }
            }
        }
    }
}

// ---------------- K6: weighted combine + residual (fp16 eo) ----------------
__global__ __launch_bounds__(256) void k_combine(
    const float* __restrict__ h, float* __restrict__ out)
{
    const int t = blockIdx.x;
    const int i = threadIdx.x;
    const float w0 = g_tokw[t * 2 + 0];
    const float w1 = g_tokw[t * 2 + 1];
    const float4 hv = ((const float4*)(h + (size_t)t * Dn))[i];
    const __half2* pa = (const __half2*)(g_eo_h + (size_t)(t * 2 + 0) * Dn);
    const __half2* pb = (const __half2*)(g_eo_h + (size_t)(t * 2 + 1) * Dn);
    float2 a0 = __half22float2(pa[i * 2]),     a1 = __half22float2(pa[i * 2 + 1]);
    float2 b0 = __half22float2(pb[i * 2]),     b1 = __half22float2(pb[i * 2 + 1]);
    float4 o;
    o.x = hv.x + w0 * a0.x + w1 * b0.x;
    o.y = hv.y + w0 * a0.y + w1 * b0.y;
    o.z = hv.z + w0 * a1.x + w1 * b1.x;
    o.w = hv.w + w0 * a1.y + w1 * b1.y;
    ((float4*)(out + (size_t)t * Dn))[i] = o;
}

// ---------------- launch ----------------
extern "C" void kernel_launch(void* const* d_in, const int* in_sizes, int n_in,
                              void* d_out, int out_size)
{
    const float* h         = (const float*)d_in[0];
    const float* feat      = (const float*)d_in[1];
    const float* ln_g      = (const float*)d_in[2];
    const float* ln_b      = (const float*)d_in[3];
    const float* Wsf       = (const float*)d_in[4];
    const float* bsf       = (const float*)d_in[5];
    const float* Wr1       = (const float*)d_in[6];
    const float* br1       = (const float*)d_in[7];
    const float* Wr2       = (const float*)d_in[8];
    const float* br2       = (const float*)d_in[9];
    const float* Wef       = (const float*)d_in[10];
    const float* bef       = (const float*)d_in[11];
    const float* We1       = (const float*)d_in[12];
    const float* be1       = (const float*)d_in[13];
    const float* We2       = (const float*)d_in[14];
    const float* be2       = (const float*)d_in[15];
    const int*   stage_idx = (const int*)d_in[16];
    const int*   expert_idx= (const int*)d_in[17];
    float* out = (float*)d_out;

    __half* We1t; cudaGetSymbolAddress((void**)&We1t, g_We1t_h);
    __half* We2t; cudaGetSymbolAddress((void**)&We2t, g_We2t_h);
    __half* Wr1th; cudaGetSymbolAddress((void**)&Wr1th, g_Wr1t_h);
    __half* Wr1tl; cudaGetSymbolAddress((void**)&Wr1tl, g_Wr1t_l);

    cudaFuncSetAttribute(k_exp_gemm_p<true>,
                         cudaFuncAttributeMaxDynamicSharedMemorySize, ESMEM);
    cudaFuncSetAttribute(k_exp_gemm_p<false>,
                         cudaFuncAttributeMaxDynamicSharedMemorySize, ESMEM);

    static cudaStream_t sW = nullptr;
    static cudaEvent_t evRoot = nullptr, evHl = nullptr, evW1 = nullptr, evW2 = nullptr;
    if (!sW) {
        cudaStreamCreateWithFlags(&sW, cudaStreamNonBlocking);
        cudaEventCreateWithFlags(&evRoot, cudaEventDisableTiming);
        cudaEventCreateWithFlags(&evHl,   cudaEventDisableTiming);
        cudaEventCreateWithFlags(&evW1,   cudaEventDisableTiming);
        cudaEventCreateWithFlags(&evW2,   cudaEventDisableTiming);
    }

    // fork: weight transposes on sW, overlapped with token path
    cudaEventRecord(evRoot, 0);
    cudaStreamWaitEvent(sW, evRoot, 0);
    k_transpose_hl<<<dim3(DRHn / 32, KINn / 32, 1), dim3(32, 8), 0, sW>>>(
        Wr1, Wr1th, Wr1tl, KINn, DRHn);
    cudaEventRecord(evHl, sW);
    k_transpose_h<<<dim3(DEHn / 32, KINn / 32, En), dim3(32, 8), 0, sW>>>(
        We1, We1t, KINn, DEHn);
    cudaEventRecord(evW1, sW);
    k_transpose_h<<<dim3(Dn / 32, DEHn / 32, En), dim3(32, 8), 0, sW>>>(
        We2, We2t, DEHn, Dn);
    cudaEventRecord(evW2, sW);

    // token path on default stream
    k_ln<<<Tn, 256>>>(h, feat, ln_g, ln_b, Wsf, bsf, stage_idx);
    cudaStreamWaitEvent(0, evHl, 0);
    k_router_gemm_split<<<dim3(DRHn / 64, Tn / 128), 256>>>(br1);
    k_router_topk<<<Tn / 8, 256>>>(Wr2, br2, feat, Wef, bef, expert_idx);
    cudaStreamWaitEvent(0, evW1, 0);
    k_exp_gemm_p<true><<<dim3(Tn / 128, DEHn / 128, En), 256, ESMEM>>>(We1t, be1);
    cudaStreamWaitEvent(0, evW2, 0);
    k_exp_gemm_p<false><<<dim3(Tn / 128, Dn / 128, En), 256, ESMEM>>>(We2t, be2);
    k_combine<<<Tn, 256>>>(h, out);
}

// round 14
// speedup vs baseline: 1.3493x; 1.0291x over previous
#include <cuda_runtime.h>
#include <cuda_fp16.h>
#include <math.h>
#include <stdint.h>

// ---------------- problem constants ----------------
#define Tn    8192          // B*S tokens
#define Dn    1024          // d_model
#define NCOLSn 32
#define FSn   16
#define NEFn  8
#define En    8
#define DFEn  64
#define DRHn  256
#define DEHn  2048
#define KINn  (Dn + DFEn)   // 1088
#define EPSf  1e-5f

// ---------------- scratch ----------------
__device__ __half g_hln_h [Tn * Dn];
__device__ __half g_hln_l [Tn * Dn];
__device__ __half g_femb_h[Tn * DFEn];
__device__ __half g_femb_l[Tn * DFEn];
__device__ float  g_hr    [Tn * DRHn];
__device__ int    g_cnt   [En];
__device__ int    g_plist [En * Tn];
__device__ int    g_toke  [Tn * 2];
__device__ float  g_tokw  [Tn * 2];
__device__ __half g_eemb_h[Tn * 2 * DFEn];
__device__ __half g_hh_h  [Tn * 2 * DEHn];
__device__ __half g_eo_h  [Tn * 2 * Dn];
__device__ __half g_We1t_h[En * (size_t)KINn * DEHn]; // [e][n][k]
__device__ __half g_We2t_h[En * (size_t)DEHn * Dn];   // [e][n][k]
__device__ __half g_Wr1t_h[(size_t)KINn * DRHn];
__device__ __half g_Wr1t_l[(size_t)KINn * DRHn];

__device__ __forceinline__ float gelu_f(float x) {
    float x3 = x * x * x;
    return 0.5f * x * (1.0f + tanhf(0.7978845608028654f * (x + 0.044715f * x3)));
}

__device__ __forceinline__ void mma_f16(float c[4], const unsigned a[4], const unsigned b[2]) {
    asm volatile(
        "mma.sync.aligned.m16n8k16.row.col.f32.f16.f16.f32 "
        "{%0,%1,%2,%3}, {%4,%5,%6,%7}, {%8,%9}, {%0,%1,%2,%3};"
        : "+f"(c[0]), "+f"(c[1]), "+f"(c[2]), "+f"(c[3])
        : "r"(a[0]), "r"(a[1]), "r"(a[2]), "r"(a[3]), "r"(b[0]), "r"(b[1]));
}

__device__ __forceinline__ uint32_t smem_u32(const void* p) {
    uint32_t a;
    asm("{ .reg .u64 t; cvta.to.shared.u64 t, %1; cvt.u32.u64 %0, t; }" : "=r"(a) : "l"(p));
    return a;
}
__device__ __forceinline__ void cp_async16(uint32_t d, const void* s, int sz) {
    asm volatile("cp.async.cg.shared.global [%0], [%1], 16, %2;"
                 :: "r"(d), "l"(s), "r"(sz) : "memory");
}

// ---------------- K0a: weight transpose+cvt  W[e][K][N] f32 -> Wt[e][N][K] f16 ----------------
__global__ __launch_bounds__(256) void k_transpose_h(
    const float* __restrict__ W, __half* __restrict__ Wt, int K, int N)
{
    __shared__ float tile[32][33];
    const int e = blockIdx.z;
    const float* Wp  = W  + (size_t)e * K * N;
    __half*      Wtp = Wt + (size_t)e * K * N;
    int x = blockIdx.x * 32 + threadIdx.x;   // n
    int y = blockIdx.y * 32 + threadIdx.y;   // k
    #pragma unroll
    for (int i = 0; i < 32; i += 8)
        tile[threadIdx.y + i][threadIdx.x] = Wp[(size_t)(y + i) * N + x];
    __syncthreads();
    x = blockIdx.y * 32 + threadIdx.x;       // k
    y = blockIdx.x * 32 + threadIdx.y;       // n
    #pragma unroll
    for (int i = 0; i < 32; i += 8)
        Wtp[(size_t)(y + i) * K + x] = __float2half(tile[threadIdx.x][threadIdx.y + i]);
}

// ---------------- K0b: transpose with hi/lo split (router W1) ----------------
__global__ __launch_bounds__(256) void k_transpose_hl(
    const float* __restrict__ W, __half* __restrict__ Wth, __half* __restrict__ Wtl,
    int K, int N)
{
    __shared__ float tile[32][33];
    int x = blockIdx.x * 32 + threadIdx.x;   // n
    int y = blockIdx.y * 32 + threadIdx.y;   // k
    #pragma unroll
    for (int i = 0; i < 32; i += 8)
        tile[threadIdx.y + i][threadIdx.x] = W[(size_t)(y + i) * N + x];
    __syncthreads();
    x = blockIdx.y * 32 + threadIdx.x;       // k
    y = blockIdx.x * 32 + threadIdx.y;       // n
    #pragma unroll
    for (int i = 0; i < 32; i += 8) {
        float v = tile[threadIdx.x][threadIdx.y + i];
        __half hi = __float2half(v);
        __half lo = __float2half(v - __half2float(hi));
        Wth[(size_t)(y + i) * K + x] = hi;
        Wtl[(size_t)(y + i) * K + x] = lo;
    }
}

// ---------------- K1: layernorm + stage-feature embedding, warp-per-token ----------------
__global__ __launch_bounds__(256) void k_ln(
    const float* __restrict__ h, const float* __restrict__ feat,
    const float* __restrict__ ln_g, const float* __restrict__ ln_b,
    const float* __restrict__ Wsf, const float* __restrict__ bsf,
    const int* __restrict__ stage_idx)
{
    const int w = threadIdx.x >> 5, l = threadIdx.x & 31;
    const int t = blockIdx.x * 8 + w;
    if (blockIdx.x == 0 && threadIdx.x < En) g_cnt[threadIdx.x] = 0;

    // each lane: 8 float4 chunks at indices l + 32*j  (MLP=8, fully coalesced)
    const float4* hp = (const float4*)(h + (size_t)t * Dn);
    float4 xv[8];
    #pragma unroll
    for (int j = 0; j < 8; j++) xv[j] = hp[l + 32 * j];

    float s = 0.f, s2 = 0.f;
    #pragma unroll
    for (int j = 0; j < 8; j++) {
        s  += xv[j].x + xv[j].y + xv[j].z + xv[j].w;
        s2 += xv[j].x * xv[j].x + xv[j].y * xv[j].y
            + xv[j].z * xv[j].z + xv[j].w * xv[j].w;
    }
    #pragma unroll
    for (int o = 16; o > 0; o >>= 1) {
        s  += __shfl_xor_sync(0xffffffffu, s,  o);
        s2 += __shfl_xor_sync(0xffffffffu, s2, o);
    }
    const float m = s * (1.0f / Dn);
    const float r = rsqrtf(s2 * (1.0f / Dn) - m * m + EPSf);

    __half2* dh = (__half2*)(g_hln_h + (size_t)t * Dn);
    __half2* dl = (__half2*)(g_hln_l + (size_t)t * Dn);
    #pragma unroll
    for (int j = 0; j < 8; j++) {
        const int i4 = l + 32 * j;
        const float4 gv = ((const float4*)ln_g)[i4];
        const float4 bv = ((const float4*)ln_b)[i4];
        float o0 = (xv[j].x - m) * r * gv.x + bv.x;
        float o1 = (xv[j].y - m) * r * gv.y + bv.y;
        float o2 = (xv[j].z - m) * r * gv.z + bv.z;
        float o3 = (xv[j].w - m) * r * gv.w + bv.w;
        __half2 h01 = __floats2half2_rn(o0, o1);
        __half2 h23 = __floats2half2_rn(o2, o3);
        float2 f01 = __half22float2(h01), f23 = __half22float2(h23);
        __half2 l01 = __floats2half2_rn(o0 - f01.x, o1 - f01.y);
        __half2 l23 = __floats2half2_rn(o2 - f23.x, o3 - f23.y);
        dh[i4 * 2 + 0] = h01; dh[i4 * 2 + 1] = h23;
        dl[i4 * 2 + 0] = l01; dl[i4 * 2 + 1] = l23;
    }

    // stage features: lane f<16 loads, broadcast via shuffle; femb dims l, l+32
    float sfv = 0.f;
    if (l < FSn) sfv = feat[(size_t)t * NCOLSn + stage_idx[l]];
    float acc0 = bsf[l], acc1 = bsf[l + 32];
    #pragma unroll
    for (int f = 0; f < FSn; f++) {
        const float v = __shfl_sync(0xffffffffu, sfv, f);
        acc0 = fmaf(v, Wsf[f * DFEn + l], acc0);
        acc1 = fmaf(v, Wsf[f * DFEn + l + 32], acc1);
    }
    __half hi0 = __float2half(acc0), hi1 = __float2half(acc1);
    g_femb_h[(size_t)t * DFEn + l]      = hi0;
    g_femb_h[(size_t)t * DFEn + l + 32] = hi1;
    g_femb_l[(size_t)t * DFEn + l]      = __float2half(acc0 - __half2float(hi0));
    g_femb_l[(size_t)t * DFEn + l + 32] = __float2half(acc1 - __half2float(hi1));
}

// ================= shared mma fragment macros (R6 layout, conflict-free LDS.32) =================
#define MMA_FRAG_A_S(dst, SM, BUF)                                                \
    _Pragma("unroll")                                                             \
    for (int mi = 0; mi < 4; mi++) {                                              \
        const int r0 = wm + mi * 16 + gid;                                        \
        dst[mi][0] = *(const unsigned*)&SM[BUF][r0][2 * tig];                     \
        dst[mi][1] = *(const unsigned*)&SM[BUF][r0 + 8][2 * tig];                 \
        dst[mi][2] = *(const unsigned*)&SM[BUF][r0][2 * tig + 8];                 \
        dst[mi][3] = *(const unsigned*)&SM[BUF][r0 + 8][2 * tig + 8];             \
    }

#define MMA_FRAG_A_P(dst, AP)                                                     \
    _Pragma("unroll")                                                             \
    for (int mi = 0; mi < 4; mi++) {                                              \
        const int r0 = wm + mi * 16 + gid;                                        \
        dst[mi][0] = *(const unsigned*)&AP[r0][2 * tig];                          \
        dst[mi][1] = *(const unsigned*)&AP[r0 + 8][2 * tig];                      \
        dst[mi][2] = *(const unsigned*)&AP[r0][2 * tig + 8];                      \
        dst[mi][3] = *(const unsigned*)&AP[r0 + 8][2 * tig + 8];                  \
    }
#define MMA_FRAG_B_P(dst, BP)                                                     \
    _Pragma("unroll")                                                             \
    for (int ni = 0; ni < 4; ni++) {                                              \
        const int nr = wn + ni * 8 + gid;                                         \
        dst[ni][0] = *(const unsigned*)&BP[nr][2 * tig];                          \
        dst[ni][1] = *(const unsigned*)&BP[nr][2 * tig + 8];                      \
    }

// ---------------- router GEMM1 (split-fp16, 128M x 64N tiles, 2 CTA/SM) ----------------
__global__ __launch_bounds__(256, 2) void k_router_gemm_split(const float* __restrict__ bias)
{
    __shared__ __half Ah[2][128][24];
    __shared__ __half Al[2][128][24];
    __shared__ __half Bh[2][64][24];
    __shared__ __half Bl[2][64][24];
    const int m0 = blockIdx.y * 128, n0 = blockIdx.x * 64;
    const int tid = threadIdx.x;
    const int warp = tid >> 5, lane = tid & 31;
    const int wm = (warp >> 2) * 64, wn = (warp & 3) * 16;
    const int gid = lane >> 2, tig = lane & 3;
    const int arow = tid >> 1, achk = (tid & 1) * 8;
    float acc[4][2][4];
    #pragma unroll
    for (int i = 0; i < 4; i++)
        #pragma unroll
        for (int j = 0; j < 2; j++)
            #pragma unroll
            for (int q = 0; q < 4; q++) acc[i][j][q] = 0.f;
    uint4 rah, ral, rbh, rbl;

    #define RLOAD(K0)                                                             \
    {                                                                             \
        const int k = (K0) + achk;                                                \
        if (k < Dn) {                                                             \
            rah = *(const uint4*)(g_hln_h + (size_t)(m0 + arow) * Dn + k);        \
            ral = *(const uint4*)(g_hln_l + (size_t)(m0 + arow) * Dn + k);        \
        } else {                                                                  \
            rah = *(const uint4*)(g_femb_h + (size_t)(m0 + arow) * DFEn + (k - Dn)); \
            ral = *(const uint4*)(g_femb_l + (size_t)(m0 + arow) * DFEn + (k - Dn)); \
        }                                                                         \
        if (tid < 128) {                                                          \
            rbh = *(const uint4*)(g_Wr1t_h + (size_t)(n0 + arow) * KINn + k);     \
            rbl = *(const uint4*)(g_Wr1t_l + (size_t)(n0 + arow) * KINn + k);     \
        }                                                                         \
    }
    #define RSTORE(BUF)                                                           \
    {                                                                             \
        *(uint4*)&Ah[BUF][arow][achk] = rah;                                      \
        *(uint4*)&Al[BUF][arow][achk] = ral;                                      \
        if (tid < 128) {                                                          \
            *(uint4*)&Bh[BUF][arow][achk] = rbh;                                  \
            *(uint4*)&Bl[BUF][arow][achk] = rbl;                                  \
        }                                                                         \
    }
    #define RCOMP(BUF)                                                            \
    {                                                                             \
        unsigned ah[4][4], al[4][4], bh[2][2], bl[2][2];                          \
        MMA_FRAG_A_S(ah, Ah, BUF)                                                 \
        MMA_FRAG_A_S(al, Al, BUF)                                                 \
        _Pragma("unroll")                                                         \
        for (int ni = 0; ni < 2; ni++) {                                          \
            const int nr = wn + ni * 8 + gid;                                     \
            bh[ni][0] = *(const unsigned*)&Bh[BUF][nr][2 * tig];                  \
            bh[ni][1] = *(const unsigned*)&Bh[BUF][nr][2 * tig + 8];              \
            bl[ni][0] = *(const unsigned*)&Bl[BUF][nr][2 * tig];                  \
            bl[ni][1] = *(const unsigned*)&Bl[BUF][nr][2 * tig + 8];              \
        }                                                                         \
        _Pragma("unroll")                                                         \
        for (int mi = 0; mi < 4; mi++)                                            \
            _Pragma("unroll")                                                     \
            for (int ni = 0; ni < 2; ni++) {                                      \
                mma_f16(acc[mi][ni], ah[mi], bh[ni]);                             \
                mma_f16(acc[mi][ni], ah[mi], bl[ni]);                             \
                mma_f16(acc[mi][ni], al[mi], bh[ni]);                             \
            }                                                                     \
    }

    const int nk = KINn / 16;  // 68
    RLOAD(0)
    RSTORE(0)
    __syncthreads();
    int buf = 0;
    for (int kt = 0; kt < nk; kt++) {
        if (kt + 1 < nk) RLOAD((kt + 1) * 16)
        RCOMP(buf)
        if (kt + 1 < nk) RSTORE(buf ^ 1)
        __syncthreads();
        buf ^= 1;
    }
    #undef RLOAD
    #undef RSTORE
    #undef RCOMP

    #pragma unroll
    for (int ni = 0; ni < 2; ni++) {
        const int c = n0 + wn + ni * 8 + 2 * tig;
        const float2 bb = *(const float2*)(bias + c);
        #pragma unroll
        for (int mi = 0; mi < 4; mi++) {
            const int r0 = m0 + wm + mi * 16 + gid;
            float2 o0, o1;
            o0.x = gelu_f(acc[mi][ni][0] + bb.x);
            o0.y = gelu_f(acc[mi][ni][1] + bb.y);
            o1.x = gelu_f(acc[mi][ni][2] + bb.x);
            o1.y = gelu_f(acc[mi][ni][3] + bb.y);
            *(float2*)(g_hr + (size_t)r0 * DRHn + c)       = o0;
            *(float2*)(g_hr + (size_t)(r0 + 8) * DRHn + c) = o1;
        }
    }
}

// ---------------- K3: logits (fp32), top-2 softmax, scatter + fused eemb ----------------
__global__ __launch_bounds__(256) void k_router_topk(
    const float* __restrict__ Wr2, const float* __restrict__ br2,
    const float* __restrict__ feat, const float* __restrict__ Wef,
    const float* __restrict__ bef, const int* __restrict__ expert_idx)
{
    __shared__ float w2s[DRHn * En];
    __shared__ float wefs[En * NEFn * DFEn];
    __shared__ float befs[En * DFEn];
    __shared__ int   eidx[En * NEFn];
    for (int i = threadIdx.x; i < DRHn * En; i += 256) w2s[i] = Wr2[i];
    for (int i = threadIdx.x; i < En * NEFn * DFEn; i += 256) wefs[i] = Wef[i];
    for (int i = threadIdx.x; i < En * DFEn; i += 256) befs[i] = bef[i];
    if (threadIdx.x < En * NEFn) eidx[threadIdx.x] = expert_idx[threadIdx.x];
    __syncthreads();

    const int w = threadIdx.x >> 5, l = threadIdx.x & 31;
    const int t = blockIdx.x * 8 + w;
    const float* hr = g_hr + (size_t)t * DRHn;

    float lg[En] = {};
    #pragma unroll
    for (int j = 0; j < DRHn / 32; j++) {
        const int k = l + 32 * j;
        const float hv = hr[k];
        #pragma unroll
        for (int e = 0; e < En; e++) lg[e] = fmaf(hv, w2s[k * En + e], lg[e]);
    }
    #pragma unroll
    for (int e = 0; e < En; e++) {
        #pragma unroll
        for (int o = 16; o > 0; o >>= 1) lg[e] += __shfl_xor_sync(0xffffffffu, lg[e], o);
    }
    int e1 = 0, e2 = -1;
    if (l == 0) {
        #pragma unroll
        for (int e = 0; e < En; e++) lg[e] += br2[e];
        float v1 = lg[0];
        #pragma unroll
        for (int e = 1; e < En; e++) if (lg[e] > v1) { v1 = lg[e]; e1 = e; }
        float v2 = -1e30f;
        #pragma unroll
        for (int e = 0; e < En; e++) if (e != e1 && lg[e] > v2) { v2 = lg[e]; e2 = e; }
        float z = expf(v2 - v1);
        float w1 = 1.0f / (1.0f + z);
        float w2 = z / (1.0f + z);
        g_toke[t * 2 + 0] = e1; g_toke[t * 2 + 1] = e2;
        g_tokw[t * 2 + 0] = w1; g_tokw[t * 2 + 1] = w2;
        int p1 = atomicAdd(&g_cnt[e1], 1); g_plist[e1 * Tn + p1] = t * 2;
        int p2 = atomicAdd(&g_cnt[e2], 1); g_plist[e2 * Tn + p2] = t * 2 + 1;
    }
    e1 = __shfl_sync(0xffffffffu, e1, 0);
    e2 = __shfl_sync(0xffffffffu, e2, 0);

    #pragma unroll
    for (int s = 0; s < 2; s++) {
        const int e = s ? e2 : e1;
        float fv[NEFn];
        #pragma unroll
        for (int f = 0; f < NEFn; f++)
            fv[f] = feat[(size_t)t * NCOLSn + eidx[e * NEFn + f]];
        #pragma unroll
        for (int half_d = 0; half_d < 2; half_d++) {
            const int d = l + half_d * 32;
            float acc = befs[e * DFEn + d];
            #pragma unroll
            for (int f = 0; f < NEFn; f++)
                acc = fmaf(fv[f], wefs[(e * NEFn + f) * DFEn + d], acc);
            g_eemb_h[(size_t)(t * 2 + s) * DFEn + d] = __float2half(acc);
        }
    }
}

// ================= expert GEMMs: cp.async 4-stage pipeline, R6 fragment layout =================
#define KT        32
#define STG       4
#define SUBBYTES  (128 * 24 * 2)          // 6144 B
#define STAGEB    (2 * SUBBYTES)          // 12288 B
#define EOFF_SROW 0
#define EOFF_A    1024
#define EOFF_B    (EOFF_A + STG * STAGEB) // 50176
#define ESMEM     (EOFF_B + STG * STAGEB) // 99328

template<bool G1>
__global__ __launch_bounds__(256, 2) void k_exp_gemm_p(
    const __half* __restrict__ Wt, const float* __restrict__ bias)
{
    constexpr int KD  = G1 ? KINn : DEHn;   // 1088 / 2048
    constexpr int NKt = KD / KT;            // 34 / 64
    constexpr int DST = G1 ? DEHn : Dn;
    const int e = blockIdx.z;
    const int cnt = g_cnt[e];
    const int m0 = blockIdx.x * 128;
    if (m0 >= cnt) return;
    const int n0 = blockIdx.y * 128;

    extern __shared__ char smem[];
    const uint32_t sb = smem_u32(smem);
    int* srow = (int*)(smem + EOFF_SROW);

    const int tid = threadIdx.x;
    const int warp = tid >> 5, lane = tid & 31;
    const int wm = (warp >> 2) * 64, wn = (warp & 3) * 32;
    const int gid = lane >> 2, tig = lane & 3;
    const int arow = tid >> 1;
    float acc[4][4][4];
    #pragma unroll
    for (int i = 0; i < 4; i++)
        #pragma unroll
        for (int j = 0; j < 4; j++)
            #pragma unroll
            for (int q = 0; q < 4; q++) acc[i][j][q] = 0.f;

    if (tid < 128) {
        int m = m0 + tid;
        srow[tid] = (m < cnt) ? g_plist[e * Tn + m] : -1;
    }
    __syncthreads();

    const int lrow = arow;           // tid >> 1
    const int lsel = (tid & 1);
    const int lslot = srow[lrow];
    const __half* Wte = Wt + (size_t)e * KD * DST;

    #define APTR(slot, k)                                                          \
        (G1 ? (((k) < Dn) ? (g_hln_h + (size_t)(((slot) < 0 ? 0 : (slot)) >> 1) * Dn + (k)) \
                          : (g_eemb_h + (size_t)((slot) < 0 ? 0 : (slot)) * DFEn + ((k) - Dn))) \
            : (g_hh_h + (size_t)((slot) < 0 ? 0 : (slot)) * DEHn + (k)))

    #define EISSUE(KTI)                                                            \
    {                                                                              \
        const int k0 = (KTI) * KT;                                                 \
        const int st = (KTI) % STG;                                                \
        const uint32_t ab = sb + EOFF_A + st * STAGEB;                             \
        const uint32_t bb = sb + EOFF_B + st * STAGEB;                             \
        _Pragma("unroll")                                                          \
        for (int s = 0; s < 2; s++) {                                              \
            const int k = k0 + s * 16 + lsel * 8;                                  \
            const uint32_t doff = (uint32_t)(s * SUBBYTES + lrow * 48 + lsel * 16);\
            cp_async16(ab + doff, APTR(lslot, k), lslot >= 0 ? 16 : 0);            \
            cp_async16(bb + doff, Wte + (size_t)(n0 + lrow) * KD + k, 16);         \
        }                                                                          \
    }

    #define ECOMP(ST)                                                              \
    {                                                                              \
        _Pragma("unroll")                                                          \
        for (int s = 0; s < 2; s++) {                                              \
            const __half (*AP)[24] = (const __half(*)[24])                         \
                (smem + EOFF_A + (ST) * STAGEB + s * SUBBYTES);                    \
            const __half (*BP)[24] = (const __half(*)[24])                         \
                (smem + EOFF_B + (ST) * STAGEB + s * SUBBYTES);                    \
            unsigned a[4][4], b[4][2];                                             \
            MMA_FRAG_A_P(a, AP)                                                    \
            MMA_FRAG_B_P(b, BP)                                                    \
            _Pragma("unroll")                                                      \
            for (int mi = 0; mi < 4; mi++)                                         \
                _Pragma("unroll")                                                  \
                for (int ni = 0; ni < 4; ni++)                                     \
                    mma_f16(acc[mi][ni], a[mi], b[ni]);                            \
        }                                                                          \
    }

    EISSUE(0)
    asm volatile("cp.async.commit_group;" ::: "memory");
    EISSUE(1)
    asm volatile("cp.async.commit_group;" ::: "memory");
    EISSUE(2)
    asm volatile("cp.async.commit_group;" ::: "memory");

    #pragma unroll 4
    for (int kt = 0; kt < NKt; kt++) {
        asm volatile("cp.async.wait_group 2;" ::: "memory");
        __syncthreads();
        if (kt + 3 < NKt) EISSUE(kt + 3)
        asm volatile("cp.async.commit_group;" ::: "memory");
        ECOMP(kt % STG)
    }
    #undef APTR
    #undef EISSUE
    #undef ECOMP

    // epilogue
    #pragma unroll
    for (int ni = 0; ni < 4; ni++) {
        const int c = n0 + wn + ni * 8 + 2 * tig;
        const float2 bb = *(const float2*)(bias + (size_t)e * DST + c);
        #pragma unroll
        for (int mi = 0; mi < 4; mi++) {
            const int r0 = wm + mi * 16 + gid;
            const int s0 = srow[r0], s1 = srow[r0 + 8];
            if (G1) {
                if (s0 >= 0) {
                    __half2 o = __floats2half2_rn(gelu_f(acc[mi][ni][0] + bb.x),
                                                  gelu_f(acc[mi][ni][1] + bb.y));
                    *(__half2*)(g_hh_h + (size_t)s0 * DEHn + c) = o;
                }
                if (s1 >= 0) {
                    __half2 o = __floats2half2_rn(gelu_f(acc[mi][ni][2] + bb.x),
                                                  gelu_f(acc[mi][ni][3] + bb.y));
                    *(__half2*)(g_hh_h + (size_t)s1 * DEHn + c) = o;
                }
            } else {
                if (s0 >= 0) {
                    __half2 o = __floats2half2_rn(acc[mi][ni][0] + bb.x,
                                                  acc[mi][ni][1] + bb.y);
                    *(__half2*)(g_eo_h + (size_t)s0 * Dn + c) = o;
                }
                if (s1 >= 0) {
                    __half2 o = __floats2half2_rn(acc[mi][ni][2] + bb.x,
                                                  acc[mi][ni][3] + bb.y);
                    *(__half2*)(g_eo_h + (size_t)s1 * Dn + c) = o;
                }
            }
        }
    }
}

// ---------------- K6: weighted combine + residual (fp16 eo) ----------------
__global__ __launch_bounds__(256) void k_combine(
    const float* __restrict__ h, float* __restrict__ out)
{
    const int t = blockIdx.x;
    const int i = threadIdx.x;
    const float w0 = g_tokw[t * 2 + 0];
    const float w1 = g_tokw[t * 2 + 1];
    const float4 hv = ((const float4*)(h + (size_t)t * Dn))[i];
    const __half2* pa = (const __half2*)(g_eo_h + (size_t)(t * 2 + 0) * Dn);
    const __half2* pb = (const __half2*)(g_eo_h + (size_t)(t * 2 + 1) * Dn);
    float2 a0 = __half22float2(pa[i * 2]),     a1 = __half22float2(pa[i * 2 + 1]);
    float2 b0 = __half22float2(pb[i * 2]),     b1 = __half22float2(pb[i * 2 + 1]);
    float4 o;
    o.x = hv.x + w0 * a0.x + w1 * b0.x;
    o.y = hv.y + w0 * a0.y + w1 * b0.y;
    o.z = hv.z + w0 * a1.x + w1 * b1.x;
    o.w = hv.w + w0 * a1.y + w1 * b1.y;
    ((float4*)(out + (size_t)t * Dn))[i] = o;
}

// ---------------- launch ----------------
extern "C" void kernel_launch(void* const* d_in, const int* in_sizes, int n_in,
                              void* d_out, int out_size)
{
    const float* h         = (const float*)d_in[0];
    const float* feat      = (const float*)d_in[1];
    const float* ln_g      = (const float*)d_in[2];
    const float* ln_b      = (const float*)d_in[3];
    const float* Wsf       = (const float*)d_in[4];
    const float* bsf       = (const float*)d_in[5];
    const float* Wr1       = (const float*)d_in[6];
    const float* br1       = (const float*)d_in[7];
    const float* Wr2       = (const float*)d_in[8];
    const float* br2       = (const float*)d_in[9];
    const float* Wef       = (const float*)d_in[10];
    const float* bef       = (const float*)d_in[11];
    const float* We1       = (const float*)d_in[12];
    const float* be1       = (const float*)d_in[13];
    const float* We2       = (const float*)d_in[14];
    const float* be2       = (const float*)d_in[15];
    const int*   stage_idx = (const int*)d_in[16];
    const int*   expert_idx= (const int*)d_in[17];
    float* out = (float*)d_out;

    __half* We1t; cudaGetSymbolAddress((void**)&We1t, g_We1t_h);
    __half* We2t; cudaGetSymbolAddress((void**)&We2t, g_We2t_h);
    __half* Wr1th; cudaGetSymbolAddress((void**)&Wr1th, g_Wr1t_h);
    __half* Wr1tl; cudaGetSymbolAddress((void**)&Wr1tl, g_Wr1t_l);

    cudaFuncSetAttribute(k_exp_gemm_p<true>,
                         cudaFuncAttributeMaxDynamicSharedMemorySize, ESMEM);
    cudaFuncSetAttribute(k_exp_gemm_p<false>,
                         cudaFuncAttributeMaxDynamicSharedMemorySize, ESMEM);

    static cudaStream_t sW = nullptr;
    static cudaEvent_t evRoot = nullptr, evHl = nullptr, evW1 = nullptr, evW2 = nullptr;
    if (!sW) {
        cudaStreamCreateWithFlags(&sW, cudaStreamNonBlocking);
        cudaEventCreateWithFlags(&evRoot, cudaEventDisableTiming);
        cudaEventCreateWithFlags(&evHl,   cudaEventDisableTiming);
        cudaEventCreateWithFlags(&evW1,   cudaEventDisableTiming);
        cudaEventCreateWithFlags(&evW2,   cudaEventDisableTiming);
    }

    // fork: weight transposes on sW, overlapped with token path
    cudaEventRecord(evRoot, 0);
    cudaStreamWaitEvent(sW, evRoot, 0);
    k_transpose_hl<<<dim3(DRHn / 32, KINn / 32, 1), dim3(32, 8), 0, sW>>>(
        Wr1, Wr1th, Wr1tl, KINn, DRHn);
    cudaEventRecord(evHl, sW);
    k_transpose_h<<<dim3(DEHn / 32, KINn / 32, En), dim3(32, 8), 0, sW>>>(
        We1, We1t, KINn, DEHn);
    cudaEventRecord(evW1, sW);
    k_transpose_h<<<dim3(Dn / 32, DEHn / 32, En), dim3(32, 8), 0, sW>>>(
        We2, We2t, DEHn, Dn);
    cudaEventRecord(evW2, sW);

    // token path on default stream
    k_ln<<<Tn / 8, 256>>>(h, feat, ln_g, ln_b, Wsf, bsf, stage_idx);
    cudaStreamWaitEvent(0, evHl, 0);
    k_router_gemm_split<<<dim3(DRHn / 64, Tn / 128), 256>>>(br1);
    k_router_topk<<<Tn / 8, 256>>>(Wr2, br2, feat, Wef, bef, expert_idx);
    cudaStreamWaitEvent(0, evW1, 0);
    k_exp_gemm_p<true><<<dim3(Tn / 128, DEHn / 128, En), 256, ESMEM>>>(We1t, be1);
    cudaStreamWaitEvent(0, evW2, 0);
    k_exp_gemm_p<false><<<dim3(Tn / 128, Dn / 128, En), 256, ESMEM>>>(We2t, be2);
    k_combine<<<Tn, 256>>>(h, out);
}